// round 12
// baseline (speedup 1.0000x reference)
#include <cuda_runtime.h>
#include <cuda_fp16.h>
#include <stdint.h>
#include <math.h>

// Problem constants
#define NROWS 16384   // B*T
#define KCB   4096    // codebook size
#define DD    256     // feature dim
#define TOPK  3

// Output layout (flattened tuple, float32)
#define OFF_LOSS   0u
#define OFF_QUANT  1u
#define OFF_PERP   12582913u
#define OFF_AVGP   12582914u
#define OFF_IDX    12587010u
#define OFF_DIST   12636162u
#define OFF_NEWCS  79745026u
#define OFF_EMAW   79749122u
#define OFF_UPD    80797698u

// Device scratch (no allocations allowed)
__device__ float g_xnorm[NROWS];
__device__ float g_enorm[KCB];
__device__ int   g_idx[NROWS * TOPK];
__device__ int   g_counts[KCB];
__device__ float g_loss;

// fp16 copies for tensor-core GEMM
__device__ __align__(128) __half g_xh[NROWS * DD];
__device__ __align__(128) __half g_eh[KCB * DD];

// per-(row, N-tile) top-3 candidate keys: [NROWS][32 tiles][3]
__device__ __align__(128) unsigned long long g_cand[NROWS * 32 * 3];

// ---------------------------------------------------------------------------
// PTX helpers
// ---------------------------------------------------------------------------
__device__ __forceinline__ uint32_t smem_u32(const void* p) {
    uint32_t a;
    asm("{ .reg .u64 t; cvta.to.shared.u64 t, %1; cvt.u32.u64 %0, t; }"
        : "=r"(a) : "l"(p));
    return a;
}
__device__ __forceinline__ void cp16(uint32_t dst, const void* src) {
    asm volatile("cp.async.cg.shared.global [%0], [%1], 16;"
                 :: "r"(dst), "l"(src) : "memory");
}
__device__ __forceinline__ void cp_commit() {
    asm volatile("cp.async.commit_group;" ::: "memory");
}
template <int N>
__device__ __forceinline__ void cp_wait() {
    asm volatile("cp.async.wait_group %0;" :: "n"(N) : "memory");
}
__device__ __forceinline__ void ldm_x4(uint32_t* r, uint32_t addr) {
    asm volatile("ldmatrix.sync.aligned.m8n8.x4.shared.b16 {%0,%1,%2,%3}, [%4];"
                 : "=r"(r[0]), "=r"(r[1]), "=r"(r[2]), "=r"(r[3]) : "r"(addr));
}
__device__ __forceinline__ void ldm_x2(uint32_t* r, uint32_t addr) {
    asm volatile("ldmatrix.sync.aligned.m8n8.x2.shared.b16 {%0,%1}, [%2];"
                 : "=r"(r[0]), "=r"(r[1]) : "r"(addr));
}
__device__ __forceinline__ void mma16816h(uint32_t* c, const uint32_t* a, const uint32_t* b) {
    asm volatile(
        "mma.sync.aligned.m16n8k16.row.col.f16.f16.f16.f16 "
        "{%0,%1}, {%2,%3,%4,%5}, {%6,%7}, {%0,%1};"
        : "+r"(c[0]), "+r"(c[1])
        : "r"(a[0]), "r"(a[1]), "r"(a[2]), "r"(a[3]), "r"(b[0]), "r"(b[1]));
}

// order-preserving float->uint map, packed with column index
__device__ __forceinline__ unsigned long long packkey(float d, int col) {
    uint32_t b = __float_as_uint(d);
    b ^= (uint32_t)(((int32_t)b) >> 31) | 0x80000000u;
    return ((unsigned long long)b << 32) | (uint32_t)col;
}
__device__ __forceinline__ void ins3k(unsigned long long v, unsigned long long* k) {
    if (v < k[2]) {
        if (v < k[0])      { k[2] = k[1]; k[1] = k[0]; k[0] = v; }
        else if (v < k[1]) { k[2] = k[1]; k[1] = v; }
        else               { k[2] = v; }
    }
}
__device__ __forceinline__ void ins8k(unsigned long long v, unsigned long long* k) {
    #pragma unroll
    for (int j = 0; j < 8; j++)
        if (v < k[j]) { unsigned long long t = k[j]; k[j] = v; v = t; }
}

// ---------------------------------------------------------------------------
// Kernel 0: single-pass norms + fp16 conversion; counts/loss zero; ema_w init
// ---------------------------------------------------------------------------
__global__ void prep_kernel(const float* __restrict__ X,
                            const float* __restrict__ E,
                            const float* __restrict__ ema_w,
                            float* __restrict__ out_emaw) {
    int tid = blockIdx.x * blockDim.x + threadIdx.x;
    int stride = gridDim.x * blockDim.x;
    if (tid < KCB) g_counts[tid] = 0;
    if (tid == 0)  g_loss = 0.0f;

    int warp = tid >> 5;
    int lane = tid & 31;
    if (warp < NROWS + KCB) {
        bool isx = warp < NROWS;
        int row = isx ? warp : warp - NROWS;
        const float4* src = (const float4*)((isx ? X : E) + (size_t)row * DD);
        float4 a = src[lane * 2];
        float4 b = src[lane * 2 + 1];
        float s = a.x * a.x + a.y * a.y + a.z * a.z + a.w * a.w
                + b.x * b.x + b.y * b.y + b.z * b.z + b.w * b.w;
        #pragma unroll
        for (int o = 16; o > 0; o >>= 1) s += __shfl_xor_sync(0xffffffffu, s, o);
        __half2 h0 = __floats2half2_rn(a.x, a.y);
        __half2 h1 = __floats2half2_rn(a.z, a.w);
        __half2 h2 = __floats2half2_rn(b.x, b.y);
        __half2 h3 = __floats2half2_rn(b.z, b.w);
        uint4 packed = make_uint4(*(uint32_t*)&h0, *(uint32_t*)&h1,
                                  *(uint32_t*)&h2, *(uint32_t*)&h3);
        ((uint4*)((isx ? g_xh : g_eh) + (size_t)row * DD))[lane] = packed;
        if (lane == 0) {
            if (isx) g_xnorm[row] = s;
            else     g_enorm[row] = s;
        }
    }

    const float2* w2 = (const float2*)ema_w;
    float2* o2 = (float2*)out_emaw;
    for (int i = tid; i < KCB * DD / 2; i += stride) {
        float2 v = w2[i];
        o2[i] = make_float2(0.99f * v.x, 0.99f * v.y);
    }
}

// ---------------------------------------------------------------------------
// Kernel 1: HMMA fp16 distance GEMM (f16 acc) + fused per-CTA top-3 epilogue
// CTA tile 128x128, BK=64, 2-stage cp.async pipeline, 8 warps (64x32 tiles)
// ---------------------------------------------------------------------------
#define BM 128
#define BN 128
#define BK 64
#define STAGE_A 16384            // 128 rows * 128 bytes
#define SMEM_GEMM (4 * 16384)    // A[2] + B[2]

__device__ __forceinline__ void load_stage(int stage, int k0, int tid,
                                           int mrow0, int nrow0, uint32_t smb) {
    const __half* ga = g_xh + (size_t)mrow0 * DD + k0;
    const __half* gb = g_eh + (size_t)nrow0 * DD + k0;
    uint32_t abase = smb + stage * STAGE_A;
    uint32_t bbase = smb + 32768 + stage * STAGE_A;
    #pragma unroll
    for (int i = 0; i < 4; i++) {
        int u = tid + i * 256;         // 0..1023 : 128 rows x 8 16B-units
        int row = u >> 3, c8 = u & 7;
        uint32_t sw = (uint32_t)((c8 ^ (row & 7)) << 4);
        cp16(abase + row * 128 + sw, ga + (size_t)row * DD + c8 * 8);
        cp16(bbase + row * 128 + sw, gb + (size_t)row * DD + c8 * 8);
    }
    cp_commit();
}

__global__ __launch_bounds__(256, 2) void gemm_dist_kernel(float* __restrict__ dist) {
    extern __shared__ char smem[];
    uint32_t smb = smem_u32(smem);
    int tid = threadIdx.x;
    int wid = tid >> 5;
    int lane = tid & 31;
    int warp_m = wid >> 2;           // 0-1 -> 64-row slab
    int warp_n = wid & 3;            // 0-3 -> 32-col slab
    int mrow0 = blockIdx.y * BM;
    int nrow0 = blockIdx.x * BN;

    uint32_t c16[4][4][2];
    #pragma unroll
    for (int i = 0; i < 4; i++)
        #pragma unroll
        for (int j = 0; j < 4; j++) { c16[i][j][0] = 0u; c16[i][j][1] = 0u; }

    load_stage(0, 0, tid, mrow0, nrow0, smb);
    load_stage(1, BK, tid, mrow0, nrow0, smb);

    #pragma unroll
    for (int kt = 0; kt < 4; kt++) {
        if (kt < 3) cp_wait<1>(); else cp_wait<0>();
        __syncthreads();

        uint32_t a_s = smb + (kt & 1) * STAGE_A;
        uint32_t b_s = smb + 32768 + (kt & 1) * STAGE_A;
        #pragma unroll
        for (int ks = 0; ks < 4; ks++) {
            uint32_t a[4][4], b[4][2];
            int arow = warp_m * 64 + (lane & 15);
            int ac8 = ks * 2 + (lane >> 4);
            #pragma unroll
            for (int i = 0; i < 4; i++) {
                int r = arow + i * 16;
                ldm_x4(a[i], a_s + r * 128 + ((ac8 ^ (r & 7)) << 4));
            }
            int brow = warp_n * 32 + (lane & 7);
            int bc8 = ks * 2 + ((lane >> 3) & 1);
            #pragma unroll
            for (int j = 0; j < 4; j++) {
                int r = brow + j * 8;
                ldm_x2(b[j], b_s + r * 128 + ((bc8 ^ (r & 7)) << 4));
            }
            #pragma unroll
            for (int i = 0; i < 4; i++)
                #pragma unroll
                for (int j = 0; j < 4; j++)
                    mma16816h(c16[i][j], a[i], b[j]);
        }
        __syncthreads();
        if (kt + 2 < 4) load_stage(kt & 1, (kt + 2) * BK, tid, mrow0, nrow0, smb);
    }

    // epilogue: dist = xn + en - 2*dot (streaming stores), plus per-CTA top-3
    float* en_s = (float*)smem;                              // 512 B
    unsigned long long* cand_s = (unsigned long long*)(smem + 1024); // [128][4][3]
    for (int i = tid; i < BN; i += 256) en_s[i] = g_enorm[nrow0 + i];
    __syncthreads();

    #pragma unroll
    for (int i = 0; i < 4; i++) {
        int r_loc0 = warp_m * 64 + i * 16 + (lane >> 2);
        int r0 = mrow0 + r_loc0;
        int r1 = r0 + 8;
        float xn0 = g_xnorm[r0];
        float xn1 = g_xnorm[r1];
        unsigned long long k0[3] = {~0ull, ~0ull, ~0ull};
        unsigned long long k1[3] = {~0ull, ~0ull, ~0ull};
        #pragma unroll
        for (int j = 0; j < 4; j++) {
            int c_loc = warp_n * 32 + j * 8 + (lane & 3) * 2;
            float en0 = en_s[c_loc], en1 = en_s[c_loc + 1];
            float2 f0 = __half22float2(*reinterpret_cast<__half2*>(&c16[i][j][0]));
            float2 f1 = __half22float2(*reinterpret_cast<__half2*>(&c16[i][j][1]));
            float2 v0 = make_float2(xn0 + en0 - 2.0f * f0.x,
                                    xn0 + en1 - 2.0f * f0.y);
            float2 v1 = make_float2(xn1 + en0 - 2.0f * f1.x,
                                    xn1 + en1 - 2.0f * f1.y);
            __stcs((float2*)(dist + (size_t)r0 * KCB + nrow0 + c_loc), v0);
            __stcs((float2*)(dist + (size_t)r1 * KCB + nrow0 + c_loc), v1);
            int cg = nrow0 + c_loc;
            ins3k(packkey(v0.x, cg), k0); ins3k(packkey(v0.y, cg + 1), k0);
            ins3k(packkey(v1.x, cg), k1); ins3k(packkey(v1.y, cg + 1), k1);
        }
        #pragma unroll
        for (int o = 1; o <= 2; o <<= 1) {
            unsigned long long ra = __shfl_xor_sync(0xffffffffu, k0[0], o);
            unsigned long long rb = __shfl_xor_sync(0xffffffffu, k0[1], o);
            unsigned long long rc = __shfl_xor_sync(0xffffffffu, k0[2], o);
            ins3k(ra, k0); ins3k(rb, k0); ins3k(rc, k0);
            ra = __shfl_xor_sync(0xffffffffu, k1[0], o);
            rb = __shfl_xor_sync(0xffffffffu, k1[1], o);
            rc = __shfl_xor_sync(0xffffffffu, k1[2], o);
            ins3k(ra, k1); ins3k(rb, k1); ins3k(rc, k1);
        }
        if ((lane & 3) == 0) {
            #pragma unroll
            for (int s = 0; s < 3; s++) {
                cand_s[r_loc0 * 12 + warp_n * 3 + s] = k0[s];
                cand_s[(r_loc0 + 8) * 12 + warp_n * 3 + s] = k1[s];
            }
        }
    }
    __syncthreads();
    if (tid < BM) {
        unsigned long long m[3] = {~0ull, ~0ull, ~0ull};
        #pragma unroll
        for (int q = 0; q < 12; q++) ins3k(cand_s[tid * 12 + q], m);
        size_t base = ((size_t)(mrow0 + tid) * 32 + blockIdx.x) * 3;
        g_cand[base + 0] = m[0];
        g_cand[base + 1] = m[1];
        g_cand[base + 2] = m[2];
    }
}

// ---------------------------------------------------------------------------
// Kernel 2: merge 96 candidates/row -> approx top-8 -> exact fp32 refine -> top-3
// One warp per row, 4 rows per block.
// ---------------------------------------------------------------------------
__global__ __launch_bounds__(128) void merge_kernel(
    const float* __restrict__ X, const float* __restrict__ E,
    float* __restrict__ out_idx_f) {
    int wq = threadIdx.x >> 5;
    int lane = threadIdx.x & 31;
    int row = blockIdx.x * 4 + wq;

    const unsigned long long* src = g_cand + (size_t)row * 96;
    unsigned long long s8[8];
    #pragma unroll
    for (int j = 0; j < 8; j++) s8[j] = ~0ull;
    ins8k(src[lane * 3 + 0], s8);
    ins8k(src[lane * 3 + 1], s8);
    ins8k(src[lane * 3 + 2], s8);

    #pragma unroll
    for (int o = 16; o > 0; o >>= 1) {
        unsigned long long r[8];
        #pragma unroll
        for (int j = 0; j < 8; j++)
            r[j] = __shfl_xor_sync(0xffffffffu, s8[j], o);
        #pragma unroll
        for (int j = 0; j < 8; j++) ins8k(r[j], s8);
    }

    __shared__ unsigned long long c8[4][8];
    __shared__ float cd[4][8];
    if (lane == 0) {
        #pragma unroll
        for (int j = 0; j < 8; j++) c8[wq][j] = s8[j];
    }
    __syncwarp();

    // exact fp32 recompute for the 8 candidates
    const float* xr = X + (size_t)row * DD;
    float xn = g_xnorm[row];
    #pragma unroll
    for (int c = 0; c < 8; c++) {
        int k = (int)(c8[wq][c] & 0xffffffffu);
        const float* er = E + (size_t)k * DD;
        float dot = 0.0f;
        #pragma unroll
        for (int j = 0; j < 8; j++)
            dot += xr[lane + j * 32] * er[lane + j * 32];
        #pragma unroll
        for (int o = 16; o > 0; o >>= 1) dot += __shfl_xor_sync(0xffffffffu, dot, o);
        if (lane == 0)
            cd[wq][c] = xn + g_enorm[k] - 2.0f * dot;
    }
    __syncwarp();

    if (lane == 0) {
        float d[8]; int ix[8];
        #pragma unroll
        for (int j = 0; j < 8; j++) {
            d[j] = cd[wq][j];
            ix[j] = (int)(c8[wq][j] & 0xffffffffu);
        }
        #pragma unroll
        for (int t = 0; t < TOPK; t++) {
            int best = t;
            #pragma unroll
            for (int j = 0; j < 8; j++) {
                if (j > t && (d[j] < d[best] || (d[j] == d[best] && ix[j] < ix[best])))
                    best = j;
            }
            float td = d[t]; d[t] = d[best]; d[best] = td;
            int ti = ix[t]; ix[t] = ix[best]; ix[best] = ti;
            g_idx[row * TOPK + t] = ix[t];
            out_idx_f[row * TOPK + t] = (float)ix[t];
        }
    }
}

// ---------------------------------------------------------------------------
// Kernel 3: gather quant_st, loss partials, counts, EMA scatter-add
// 4 rows/block x 64 threads/row; float4 loads, scalar streaming stores
// ---------------------------------------------------------------------------
__global__ __launch_bounds__(256) void gather_kernel(
    const float* __restrict__ X, const float* __restrict__ E,
    float* __restrict__ out) {
    int tid = threadIdx.x;
    int rl = tid >> 6;           // 0..3 row within block
    int d4 = tid & 63;           // float4 index within row (D=256 -> 64)
    int row = blockIdx.x * 4 + rl;

    __shared__ int sidx[12];
    if (tid < 12) sidx[tid] = g_idx[blockIdx.x * 12 + tid];
    __syncthreads();

    const float4* X4 = (const float4*)X;
    const float4* E4 = (const float4*)E;
    float4 xv = X4[(size_t)row * 64 + d4];
    float sumsq = 0.0f;
    #pragma unroll
    for (int j = 0; j < 3; j++) {
        int k = sidx[rl * 3 + j];
        float4 ev = E4[(size_t)k * 64 + d4];
        float* q = &out[OFF_QUANT + ((size_t)row * 3 + j) * DD + d4 * 4];
        __stcs(q + 0, ev.x); __stcs(q + 1, ev.y);
        __stcs(q + 2, ev.z); __stcs(q + 3, ev.w);
        float dx = ev.x - xv.x, dy = ev.y - xv.y;
        float dz = ev.z - xv.z, dw = ev.w - xv.w;
        sumsq += dx * dx + dy * dy + dz * dz + dw * dw;
        float* w = &out[OFF_EMAW + (size_t)k * DD + d4 * 4];
        atomicAdd(w + 0, 0.01f * xv.x);
        atomicAdd(w + 1, 0.01f * xv.y);
        atomicAdd(w + 2, 0.01f * xv.z);
        atomicAdd(w + 3, 0.01f * xv.w);
    }
    if (tid < 12) atomicAdd(&g_counts[sidx[tid]], 1);

    #pragma unroll
    for (int o = 16; o > 0; o >>= 1) sumsq += __shfl_xor_sync(0xffffffffu, sumsq, o);
    __shared__ float red[8];
    if ((tid & 31) == 0) red[tid >> 5] = sumsq;
    __syncthreads();
    if (tid == 0) {
        float t = 0.0f;
        #pragma unroll
        for (int i = 0; i < 8; i++) t += red[i];
        atomicAdd(&g_loss, t);
    }
}

// ---------------------------------------------------------------------------
// Kernel 4: new_cs, avg_probs, perplexity, loss
// ---------------------------------------------------------------------------
__global__ __launch_bounds__(1024) void finalize_kernel(
    const float* __restrict__ ema_cs, float* __restrict__ out) {
    int tid = threadIdx.x;
    float nsum = 0.0f, plp = 0.0f;
    for (int k = tid; k < KCB; k += 1024) {
        float pre = ema_cs[k] * 0.99f + 0.01f * (float)g_counts[k];
        nsum += pre;
        float p = (float)g_counts[k] * (1.0f / 16384.0f);
        plp += p * __logf(p + 1e-10f);
    }
    __shared__ float sN[32], sP[32];
    #pragma unroll
    for (int o = 16; o > 0; o >>= 1) {
        nsum += __shfl_xor_sync(0xffffffffu, nsum, o);
        plp  += __shfl_xor_sync(0xffffffffu, plp, o);
    }
    if ((tid & 31) == 0) { sN[tid >> 5] = nsum; sP[tid >> 5] = plp; }
    __syncthreads();
    if (tid < 32) {
        float a = sN[tid], b = sP[tid];
        #pragma unroll
        for (int o = 16; o > 0; o >>= 1) {
            a += __shfl_xor_sync(0xffffffffu, a, o);
            b += __shfl_xor_sync(0xffffffffu, b, o);
        }
        if (tid == 0) { sN[0] = a; sP[0] = b; }
    }
    __syncthreads();
    float nfin = sN[0];
    float plpt = sP[0];
    float scale = nfin / (nfin + (float)KCB * 1e-5f);
    for (int k = tid; k < KCB; k += 1024) {
        float pre = ema_cs[k] * 0.99f + 0.01f * (float)g_counts[k];
        out[OFF_NEWCS + k] = (pre + 1e-5f) * scale;
        out[OFF_AVGP + k] = (float)g_counts[k] * (1.0f / 16384.0f);
    }
    if (tid == 0) {
        out[OFF_LOSS] = 0.25f * g_loss * (1.0f / (16384.0f * 3.0f * 256.0f));
        out[OFF_PERP] = __expf(-plpt);
    }
}

// ---------------------------------------------------------------------------
// Kernel 5: updated_embeddings = new_ema_w / new_cs (float2 vectorized)
// ---------------------------------------------------------------------------
__global__ __launch_bounds__(256) void upd_kernel(float* __restrict__ out) {
    int t = blockIdx.x * blockDim.x + threadIdx.x;   // float2 units
    if (t < KCB * DD / 2) {
        float2 w = *(const float2*)&out[OFF_EMAW + (size_t)t * 2];
        float cs = out[OFF_NEWCS + (t >> 7)];        // (t*2)>>8
        *(float2*)&out[OFF_UPD + (size_t)t * 2] = make_float2(w.x / cs, w.y / cs);
    }
}

// ---------------------------------------------------------------------------
extern "C" void kernel_launch(void* const* d_in, const int* in_sizes, int n_in,
                              void* d_out, int out_size) {
    const float* X      = (const float*)d_in[0];
    const float* E      = (const float*)d_in[1];
    const float* ema_cs = (const float*)d_in[2];
    const float* ema_w  = (const float*)d_in[3];
    float* out = (float*)d_out;
    (void)in_sizes; (void)n_in; (void)out_size;

    cudaFuncSetAttribute(gemm_dist_kernel,
                         cudaFuncAttributeMaxDynamicSharedMemorySize, SMEM_GEMM);

    prep_kernel<<<2560, 256>>>(X, E, ema_w, out + OFF_EMAW);

    dim3 ggrid(KCB / BN, NROWS / BM);  // (32, 128)
    gemm_dist_kernel<<<ggrid, 256, SMEM_GEMM>>>(out + OFF_DIST);

    merge_kernel<<<NROWS / 4, 128>>>(X, E, out + OFF_IDX);

    gather_kernel<<<NROWS / 4, 256>>>(X, E, out);

    finalize_kernel<<<1, 1024>>>(ema_cs, out);

    upd_kernel<<<(KCB * DD / 2 + 255) / 256, 256>>>(out);
}

// round 15
// speedup vs baseline: 1.1160x; 1.1160x over previous
#include <cuda_runtime.h>
#include <cuda_fp16.h>
#include <stdint.h>
#include <math.h>

// Problem constants
#define NROWS 16384   // B*T
#define KCB   4096    // codebook size
#define DD    256     // feature dim
#define TOPK  3

// Output layout (flattened tuple, float32)
#define OFF_LOSS   0u
#define OFF_QUANT  1u
#define OFF_PERP   12582913u
#define OFF_AVGP   12582914u
#define OFF_IDX    12587010u
#define OFF_DIST   12636162u
#define OFF_NEWCS  79745026u
#define OFF_EMAW   79749122u
#define OFF_UPD    80797698u

// Device scratch (no allocations allowed)
__device__ float g_xnorm[NROWS];
__device__ float g_enorm[KCB];
__device__ int   g_idx[NROWS * TOPK];
__device__ int   g_counts[KCB];
__device__ float g_loss;

// fp16 copies for tensor-core GEMM
__device__ __align__(128) __half g_xh[NROWS * DD];
__device__ __align__(128) __half g_eh[KCB * DD];

// per-(row, N-tile) top-3 candidate keys: [NROWS][32 tiles][3]
__device__ __align__(128) unsigned long long g_cand[NROWS * 32 * 3];

// ---------------------------------------------------------------------------
// PTX helpers
// ---------------------------------------------------------------------------
__device__ __forceinline__ uint32_t smem_u32(const void* p) {
    uint32_t a;
    asm("{ .reg .u64 t; cvta.to.shared.u64 t, %1; cvt.u32.u64 %0, t; }"
        : "=r"(a) : "l"(p));
    return a;
}
__device__ __forceinline__ void cp16(uint32_t dst, const void* src) {
    asm volatile("cp.async.cg.shared.global [%0], [%1], 16;"
                 :: "r"(dst), "l"(src) : "memory");
}
__device__ __forceinline__ void cp_commit() {
    asm volatile("cp.async.commit_group;" ::: "memory");
}
template <int N>
__device__ __forceinline__ void cp_wait() {
    asm volatile("cp.async.wait_group %0;" :: "n"(N) : "memory");
}
__device__ __forceinline__ void ldm_x4(uint32_t* r, uint32_t addr) {
    asm volatile("ldmatrix.sync.aligned.m8n8.x4.shared.b16 {%0,%1,%2,%3}, [%4];"
                 : "=r"(r[0]), "=r"(r[1]), "=r"(r[2]), "=r"(r[3]) : "r"(addr));
}
__device__ __forceinline__ void ldm_x2(uint32_t* r, uint32_t addr) {
    asm volatile("ldmatrix.sync.aligned.m8n8.x2.shared.b16 {%0,%1}, [%2];"
                 : "=r"(r[0]), "=r"(r[1]) : "r"(addr));
}
__device__ __forceinline__ void mma16816h(uint32_t* c, const uint32_t* a, const uint32_t* b) {
    asm volatile(
        "mma.sync.aligned.m16n8k16.row.col.f16.f16.f16.f16 "
        "{%0,%1}, {%2,%3,%4,%5}, {%6,%7}, {%0,%1};"
        : "+r"(c[0]), "+r"(c[1])
        : "r"(a[0]), "r"(a[1]), "r"(a[2]), "r"(a[3]), "r"(b[0]), "r"(b[1]));
}

// order-preserving float->uint map, packed with column index
__device__ __forceinline__ unsigned long long packkey(float d, int col) {
    uint32_t b = __float_as_uint(d);
    b ^= (uint32_t)(((int32_t)b) >> 31) | 0x80000000u;
    return ((unsigned long long)b << 32) | (uint32_t)col;
}
__device__ __forceinline__ void ins3k(unsigned long long v, unsigned long long* k) {
    if (v < k[2]) {
        if (v < k[0])      { k[2] = k[1]; k[1] = k[0]; k[0] = v; }
        else if (v < k[1]) { k[2] = k[1]; k[1] = v; }
        else               { k[2] = v; }
    }
}
__device__ __forceinline__ void ins8k(unsigned long long v, unsigned long long* k) {
    #pragma unroll
    for (int j = 0; j < 8; j++)
        if (v < k[j]) { unsigned long long t = k[j]; k[j] = v; v = t; }
}

// ---------------------------------------------------------------------------
// Kernel 0: single-pass norms + fp16 conversion; counts/loss zero; ema_w init
// ---------------------------------------------------------------------------
__global__ void prep_kernel(const float* __restrict__ X,
                            const float* __restrict__ E,
                            const float* __restrict__ ema_w,
                            float* __restrict__ out_emaw) {
    int tid = blockIdx.x * blockDim.x + threadIdx.x;
    int stride = gridDim.x * blockDim.x;
    if (tid < KCB) g_counts[tid] = 0;
    if (tid == 0)  g_loss = 0.0f;

    int warp = tid >> 5;
    int lane = tid & 31;
    if (warp < NROWS + KCB) {
        bool isx = warp < NROWS;
        int row = isx ? warp : warp - NROWS;
        const float4* src = (const float4*)((isx ? X : E) + (size_t)row * DD);
        float4 a = src[lane * 2];
        float4 b = src[lane * 2 + 1];
        float s = a.x * a.x + a.y * a.y + a.z * a.z + a.w * a.w
                + b.x * b.x + b.y * b.y + b.z * b.z + b.w * b.w;
        #pragma unroll
        for (int o = 16; o > 0; o >>= 1) s += __shfl_xor_sync(0xffffffffu, s, o);
        __half2 h0 = __floats2half2_rn(a.x, a.y);
        __half2 h1 = __floats2half2_rn(a.z, a.w);
        __half2 h2 = __floats2half2_rn(b.x, b.y);
        __half2 h3 = __floats2half2_rn(b.z, b.w);
        uint4 packed = make_uint4(*(uint32_t*)&h0, *(uint32_t*)&h1,
                                  *(uint32_t*)&h2, *(uint32_t*)&h3);
        ((uint4*)((isx ? g_xh : g_eh) + (size_t)row * DD))[lane] = packed;
        if (lane == 0) {
            if (isx) g_xnorm[row] = s;
            else     g_enorm[row] = s;
        }
    }

    const float2* w2 = (const float2*)ema_w;
    float2* o2 = (float2*)out_emaw;
    for (int i = tid; i < KCB * DD / 2; i += stride) {
        float2 v = w2[i];
        o2[i] = make_float2(0.99f * v.x, 0.99f * v.y);
    }
}

// ---------------------------------------------------------------------------
// Kernel 1: HMMA fp16 distance GEMM (f16 acc) + fused per-CTA top-3 epilogue
// CTA tile 128x128, BK=64, 2-stage cp.async pipeline, 8 warps (64x32 tiles)
// ---------------------------------------------------------------------------
#define BM 128
#define BN 128
#define BK 64
#define STAGE_A 16384            // 128 rows * 128 bytes
#define SMEM_GEMM (4 * 16384)    // A[2] + B[2]

__device__ __forceinline__ void load_stage(int stage, int k0, int tid,
                                           int mrow0, int nrow0, uint32_t smb) {
    const __half* ga = g_xh + (size_t)mrow0 * DD + k0;
    const __half* gb = g_eh + (size_t)nrow0 * DD + k0;
    uint32_t abase = smb + stage * STAGE_A;
    uint32_t bbase = smb + 32768 + stage * STAGE_A;
    #pragma unroll
    for (int i = 0; i < 4; i++) {
        int u = tid + i * 256;         // 0..1023 : 128 rows x 8 16B-units
        int row = u >> 3, c8 = u & 7;
        uint32_t sw = (uint32_t)((c8 ^ (row & 7)) << 4);
        cp16(abase + row * 128 + sw, ga + (size_t)row * DD + c8 * 8);
        cp16(bbase + row * 128 + sw, gb + (size_t)row * DD + c8 * 8);
    }
    cp_commit();
}

__global__ __launch_bounds__(256, 2) void gemm_dist_kernel(float* __restrict__ dist) {
    extern __shared__ char smem[];
    uint32_t smb = smem_u32(smem);
    int tid = threadIdx.x;
    int wid = tid >> 5;
    int lane = tid & 31;
    int warp_m = wid >> 2;           // 0-1 -> 64-row slab
    int warp_n = wid & 3;            // 0-3 -> 32-col slab
    int mrow0 = blockIdx.y * BM;
    int nrow0 = blockIdx.x * BN;

    uint32_t c16[4][4][2];
    #pragma unroll
    for (int i = 0; i < 4; i++)
        #pragma unroll
        for (int j = 0; j < 4; j++) { c16[i][j][0] = 0u; c16[i][j][1] = 0u; }

    load_stage(0, 0, tid, mrow0, nrow0, smb);
    load_stage(1, BK, tid, mrow0, nrow0, smb);

    #pragma unroll
    for (int kt = 0; kt < 4; kt++) {
        if (kt < 3) cp_wait<1>(); else cp_wait<0>();
        __syncthreads();

        uint32_t a_s = smb + (kt & 1) * STAGE_A;
        uint32_t b_s = smb + 32768 + (kt & 1) * STAGE_A;
        #pragma unroll
        for (int ks = 0; ks < 4; ks++) {
            uint32_t a[4][4], b[4][2];
            int arow = warp_m * 64 + (lane & 15);
            int ac8 = ks * 2 + (lane >> 4);
            #pragma unroll
            for (int i = 0; i < 4; i++) {
                int r = arow + i * 16;
                ldm_x4(a[i], a_s + r * 128 + ((ac8 ^ (r & 7)) << 4));
            }
            int brow = warp_n * 32 + (lane & 7);
            int bc8 = ks * 2 + ((lane >> 3) & 1);
            #pragma unroll
            for (int j = 0; j < 4; j++) {
                int r = brow + j * 8;
                ldm_x2(b[j], b_s + r * 128 + ((bc8 ^ (r & 7)) << 4));
            }
            #pragma unroll
            for (int i = 0; i < 4; i++)
                #pragma unroll
                for (int j = 0; j < 4; j++)
                    mma16816h(c16[i][j], a[i], b[j]);
        }
        __syncthreads();
        if (kt + 2 < 4) load_stage(kt & 1, (kt + 2) * BK, tid, mrow0, nrow0, smb);
    }

    // epilogue: dist = xn + en - 2*dot (streaming stores), plus per-CTA top-3
    float* en_s = (float*)smem;                              // 512 B
    unsigned long long* cand_s = (unsigned long long*)(smem + 1024); // [128][4][3]
    for (int i = tid; i < BN; i += 256) en_s[i] = g_enorm[nrow0 + i];
    __syncthreads();

    #pragma unroll
    for (int i = 0; i < 4; i++) {
        int r_loc0 = warp_m * 64 + i * 16 + (lane >> 2);
        int r0 = mrow0 + r_loc0;
        int r1 = r0 + 8;
        float xn0 = g_xnorm[r0];
        float xn1 = g_xnorm[r1];
        unsigned long long k0[3] = {~0ull, ~0ull, ~0ull};
        unsigned long long k1[3] = {~0ull, ~0ull, ~0ull};
        #pragma unroll
        for (int j = 0; j < 4; j++) {
            int c_loc = warp_n * 32 + j * 8 + (lane & 3) * 2;
            float en0 = en_s[c_loc], en1 = en_s[c_loc + 1];
            float2 f0 = __half22float2(*reinterpret_cast<__half2*>(&c16[i][j][0]));
            float2 f1 = __half22float2(*reinterpret_cast<__half2*>(&c16[i][j][1]));
            float2 v0 = make_float2(xn0 + en0 - 2.0f * f0.x,
                                    xn0 + en1 - 2.0f * f0.y);
            float2 v1 = make_float2(xn1 + en0 - 2.0f * f1.x,
                                    xn1 + en1 - 2.0f * f1.y);
            __stcs((float2*)(dist + (size_t)r0 * KCB + nrow0 + c_loc), v0);
            __stcs((float2*)(dist + (size_t)r1 * KCB + nrow0 + c_loc), v1);
            int cg = nrow0 + c_loc;
            ins3k(packkey(v0.x, cg), k0); ins3k(packkey(v0.y, cg + 1), k0);
            ins3k(packkey(v1.x, cg), k1); ins3k(packkey(v1.y, cg + 1), k1);
        }
        #pragma unroll
        for (int o = 1; o <= 2; o <<= 1) {
            unsigned long long ra = __shfl_xor_sync(0xffffffffu, k0[0], o);
            unsigned long long rb = __shfl_xor_sync(0xffffffffu, k0[1], o);
            unsigned long long rc = __shfl_xor_sync(0xffffffffu, k0[2], o);
            ins3k(ra, k0); ins3k(rb, k0); ins3k(rc, k0);
            ra = __shfl_xor_sync(0xffffffffu, k1[0], o);
            rb = __shfl_xor_sync(0xffffffffu, k1[1], o);
            rc = __shfl_xor_sync(0xffffffffu, k1[2], o);
            ins3k(ra, k1); ins3k(rb, k1); ins3k(rc, k1);
        }
        if ((lane & 3) == 0) {
            #pragma unroll
            for (int s = 0; s < 3; s++) {
                cand_s[r_loc0 * 12 + warp_n * 3 + s] = k0[s];
                cand_s[(r_loc0 + 8) * 12 + warp_n * 3 + s] = k1[s];
            }
        }
    }
    __syncthreads();
    if (tid < BM) {
        unsigned long long m[3] = {~0ull, ~0ull, ~0ull};
        #pragma unroll
        for (int q = 0; q < 12; q++) ins3k(cand_s[tid * 12 + q], m);
        size_t base = ((size_t)(mrow0 + tid) * 32 + blockIdx.x) * 3;
        g_cand[base + 0] = m[0];
        g_cand[base + 1] = m[1];
        g_cand[base + 2] = m[2];
    }
}

// ---------------------------------------------------------------------------
// Kernel 2: merge 96 candidates/row -> approx top-8 -> exact fp32 refine -> top-3
// One warp per row, 4 rows per block.
// ---------------------------------------------------------------------------
__global__ __launch_bounds__(128) void merge_kernel(
    const float* __restrict__ X, const float* __restrict__ E,
    float* __restrict__ out_idx_f) {
    int wq = threadIdx.x >> 5;
    int lane = threadIdx.x & 31;
    int row = blockIdx.x * 4 + wq;

    const unsigned long long* src = g_cand + (size_t)row * 96;
    unsigned long long s8[8];
    #pragma unroll
    for (int j = 0; j < 8; j++) s8[j] = ~0ull;
    ins8k(src[lane * 3 + 0], s8);
    ins8k(src[lane * 3 + 1], s8);
    ins8k(src[lane * 3 + 2], s8);

    #pragma unroll
    for (int o = 16; o > 0; o >>= 1) {
        unsigned long long r[8];
        #pragma unroll
        for (int j = 0; j < 8; j++)
            r[j] = __shfl_xor_sync(0xffffffffu, s8[j], o);
        #pragma unroll
        for (int j = 0; j < 8; j++) ins8k(r[j], s8);
    }

    __shared__ unsigned long long c8[4][8];
    __shared__ float cd[4][8];
    if (lane == 0) {
        #pragma unroll
        for (int j = 0; j < 8; j++) c8[wq][j] = s8[j];
    }
    __syncwarp();

    // exact fp32 recompute for the 8 candidates
    const float* xr = X + (size_t)row * DD;
    float xn = g_xnorm[row];
    #pragma unroll
    for (int c = 0; c < 8; c++) {
        int k = (int)(c8[wq][c] & 0xffffffffu);
        const float* er = E + (size_t)k * DD;
        float dot = 0.0f;
        #pragma unroll
        for (int j = 0; j < 8; j++)
            dot += xr[lane + j * 32] * er[lane + j * 32];
        #pragma unroll
        for (int o = 16; o > 0; o >>= 1) dot += __shfl_xor_sync(0xffffffffu, dot, o);
        if (lane == 0)
            cd[wq][c] = xn + g_enorm[k] - 2.0f * dot;
    }
    __syncwarp();

    if (lane == 0) {
        float d[8]; int ix[8];
        #pragma unroll
        for (int j = 0; j < 8; j++) {
            d[j] = cd[wq][j];
            ix[j] = (int)(c8[wq][j] & 0xffffffffu);
        }
        #pragma unroll
        for (int t = 0; t < TOPK; t++) {
            int best = t;
            #pragma unroll
            for (int j = 0; j < 8; j++) {
                if (j > t && (d[j] < d[best] || (d[j] == d[best] && ix[j] < ix[best])))
                    best = j;
            }
            float td = d[t]; d[t] = d[best]; d[best] = td;
            int ti = ix[t]; ix[t] = ix[best]; ix[best] = ti;
            g_idx[row * TOPK + t] = ix[t];
            out_idx_f[row * TOPK + t] = (float)ix[t];
        }
    }
}

// ---------------------------------------------------------------------------
// Kernel 3: gather quant_st, loss partials, counts, EMA scatter-add
// (round-11 proven shape: one block of 256 threads per row, scalar ops)
// ---------------------------------------------------------------------------
__global__ __launch_bounds__(256) void gather_kernel(
    const float* __restrict__ X, const float* __restrict__ E,
    float* __restrict__ out) {
    int n = blockIdx.x;
    int d = threadIdx.x;
    float xv = X[(size_t)n * DD + d];
    int ks[3] = {g_idx[n * 3 + 0], g_idx[n * 3 + 1], g_idx[n * 3 + 2]};

    float sumsq = 0.0f;
    #pragma unroll
    for (int j = 0; j < 3; j++) {
        int k = ks[j];
        float ev = E[(size_t)k * DD + d];
        out[OFF_QUANT + ((size_t)n * 3 + j) * DD + d] = ev;
        float diff = ev - xv;
        sumsq += diff * diff;
        atomicAdd(&out[OFF_EMAW + (size_t)k * DD + d], 0.01f * xv);
    }
    if (d < 3) atomicAdd(&g_counts[ks[d]], 1);

    #pragma unroll
    for (int o = 16; o > 0; o >>= 1) sumsq += __shfl_xor_sync(0xffffffffu, sumsq, o);
    __shared__ float red[8];
    if ((d & 31) == 0) red[d >> 5] = sumsq;
    __syncthreads();
    if (d == 0) {
        float t = 0.0f;
        #pragma unroll
        for (int i = 0; i < 8; i++) t += red[i];
        atomicAdd(&g_loss, t);
    }
}

// ---------------------------------------------------------------------------
// Kernel 4: new_cs, avg_probs, perplexity, loss (fast-math log/exp)
// ---------------------------------------------------------------------------
__global__ __launch_bounds__(1024) void finalize_kernel(
    const float* __restrict__ ema_cs, float* __restrict__ out) {
    int tid = threadIdx.x;
    float nsum = 0.0f, plp = 0.0f;
    for (int k = tid; k < KCB; k += 1024) {
        float pre = ema_cs[k] * 0.99f + 0.01f * (float)g_counts[k];
        nsum += pre;
        float p = (float)g_counts[k] * (1.0f / 16384.0f);
        plp += p * __logf(p + 1e-10f);
    }
    __shared__ float sN[32], sP[32];
    #pragma unroll
    for (int o = 16; o > 0; o >>= 1) {
        nsum += __shfl_xor_sync(0xffffffffu, nsum, o);
        plp  += __shfl_xor_sync(0xffffffffu, plp, o);
    }
    if ((tid & 31) == 0) { sN[tid >> 5] = nsum; sP[tid >> 5] = plp; }
    __syncthreads();
    if (tid < 32) {
        float a = sN[tid], b = sP[tid];
        #pragma unroll
        for (int o = 16; o > 0; o >>= 1) {
            a += __shfl_xor_sync(0xffffffffu, a, o);
            b += __shfl_xor_sync(0xffffffffu, b, o);
        }
        if (tid == 0) { sN[0] = a; sP[0] = b; }
    }
    __syncthreads();
    float nfin = sN[0];
    float plpt = sP[0];
    float scale = nfin / (nfin + (float)KCB * 1e-5f);
    for (int k = tid; k < KCB; k += 1024) {
        float pre = ema_cs[k] * 0.99f + 0.01f * (float)g_counts[k];
        out[OFF_NEWCS + k] = (pre + 1e-5f) * scale;
        out[OFF_AVGP + k] = (float)g_counts[k] * (1.0f / 16384.0f);
    }
    if (tid == 0) {
        out[OFF_LOSS] = 0.25f * g_loss * (1.0f / (16384.0f * 3.0f * 256.0f));
        out[OFF_PERP] = __expf(-plpt);
    }
}

// ---------------------------------------------------------------------------
// Kernel 5: updated_embeddings = new_ema_w / new_cs (float2 vectorized)
// ---------------------------------------------------------------------------
__global__ __launch_bounds__(256) void upd_kernel(float* __restrict__ out) {
    int t = blockIdx.x * blockDim.x + threadIdx.x;   // float2 units
    if (t < KCB * DD / 2) {
        float2 w = *(const float2*)&out[OFF_EMAW + (size_t)t * 2];
        float cs = out[OFF_NEWCS + (t >> 7)];        // (t*2)>>8
        *(float2*)&out[OFF_UPD + (size_t)t * 2] = make_float2(w.x / cs, w.y / cs);
    }
}

// ---------------------------------------------------------------------------
extern "C" void kernel_launch(void* const* d_in, const int* in_sizes, int n_in,
                              void* d_out, int out_size) {
    const float* X      = (const float*)d_in[0];
    const float* E      = (const float*)d_in[1];
    const float* ema_cs = (const float*)d_in[2];
    const float* ema_w  = (const float*)d_in[3];
    float* out = (float*)d_out;
    (void)in_sizes; (void)n_in; (void)out_size;

    cudaFuncSetAttribute(gemm_dist_kernel,
                         cudaFuncAttributeMaxDynamicSharedMemorySize, SMEM_GEMM);

    prep_kernel<<<2560, 256>>>(X, E, ema_w, out + OFF_EMAW);

    dim3 ggrid(KCB / BN, NROWS / BM);  // (32, 128)
    gemm_dist_kernel<<<ggrid, 256, SMEM_GEMM>>>(out + OFF_DIST);

    merge_kernel<<<NROWS / 4, 128>>>(X, E, out + OFF_IDX);

    gather_kernel<<<NROWS, 256>>>(X, E, out);

    finalize_kernel<<<1, 1024>>>(ema_cs, out);

    upd_kernel<<<(KCB * DD / 2 + 255) / 256, 256>>>(out);
}